// round 11
// baseline (speedup 1.0000x reference)
#include <cuda_runtime.h>
#include <math.h>

// Problem constants (B=1, C_IN=3, H=W=96, FEAT=64, GDIM=8, BLOCK=16)
#define Hh   96
#define Ww   96
#define HW   (96 * 96)
#define GD   8
#define FEAT 64
#define CIN  3

#define NBX  12            // 12x12 tiles of 8x8 pixels
#define NB   (NBX * NBX)   // 144 blocks (<=148 SMs -> co-resident, barrier safe)
#define NT   512
#define PT   8             // pixel tile edge
#define IT   10            // input patch edge (PT + 2 conv halo)

#define LN255 5.5412635f   // ln(255); alpha >= 1/255  <=>  sigma <= ln(255)

// 32-byte gaussian record (tile-bounds test proven redundant: radius >= 2
// always, and any sigma-gate survivor has |d| <= 1.665 < radius).
struct __align__(16) GParam {
    float cx, cy, ca, cb, cc, r0, r1, r2;
};

__device__ GParam g_gauss[HW];   // 288 KB scratch (device global: no allocations)
__device__ int    g_count = 0;   // sense-reversing barrier (self-restoring)
__device__ int    g_sense = 0;

// ---------------------------------------------------------------------------
// One fused kernel: stage -> collapse -> conv(from shared) -> activations ->
// sense-reversing grid barrier -> raster over the EXACT 5x5 window.
// Each block owns one 8x8 pixel tile; gaussians computed exactly once.
// ---------------------------------------------------------------------------
__global__ __launch_bounds__(NT)
void fused_kernel(const float* __restrict__ inp,
                  const float* __restrict__ w_enc,
                  const float* __restrict__ b_enc,
                  const float* __restrict__ w_head,
                  const float* __restrict__ b_head,
                  float* __restrict__ out)
{
    __shared__ float s_we[FEAT * 27];      // w_enc [c*27 + k]
    __shared__ float s_wh[FEAT * GD];      // w_head transposed [c*8 + o]
    __shared__ float s_be[FEAT];
    __shared__ float s_bh[GD];
    __shared__ float sw[GD * 27];          // collapsed weights
    __shared__ float sb[GD];
    __shared__ float s_inp[CIN][IT][IT];   // zero-padded 10x10x3 input patch
    __shared__ float spred[64 * 9];        // raw preds, stride 9 (bank-friendly)

    const int tid = threadIdx.x;
    const int r0 = (blockIdx.x / NBX) * PT;   // tile origin row
    const int c0 = (blockIdx.x % NBX) * PT;   // tile origin col

    // ---- stage weights + input patch ---------------------------------------
    for (int t = tid; t < FEAT * 27; t += NT) s_we[t] = __ldg(&w_enc[t]);
    {   // transpose w_head into [c][o]  (tid < 512 == FEAT*GD)
        const int c = tid >> 3, o = tid & 7;
        s_wh[c * GD + o] = __ldg(&w_head[o * FEAT + c]);
    }
    if (tid < FEAT) s_be[tid] = __ldg(&b_enc[tid]);
    if (tid < GD)   s_bh[tid] = __ldg(&b_head[tid]);

    for (int t = tid; t < CIN * IT * IT; t += NT) {
        const int ci = t / (IT * IT);
        const int rr = (t / IT) % IT;
        const int cc = t % IT;
        const int y = r0 - 1 + rr;
        const int x = c0 - 1 + cc;
        float v = 0.f;
        if ((unsigned)y < Hh && (unsigned)x < Ww)
            v = __ldg(&inp[ci * HW + y * Ww + x]);
        s_inp[ci][rr][cc] = v;
    }
    __syncthreads();

    // ---- collapse conv+head ------------------------------------------------
    if (tid < GD * 27) {
        const int o = tid / 27, k = tid % 27;
        float a0 = 0.f, a1 = 0.f, a2 = 0.f, a3 = 0.f;
        #pragma unroll
        for (int c = 0; c < FEAT; c += 4) {
            a0 += s_wh[(c    ) * GD + o] * s_we[(c    ) * 27 + k];
            a1 += s_wh[(c + 1) * GD + o] * s_we[(c + 1) * 27 + k];
            a2 += s_wh[(c + 2) * GD + o] * s_we[(c + 2) * 27 + k];
            a3 += s_wh[(c + 3) * GD + o] * s_we[(c + 3) * 27 + k];
        }
        sw[tid] = (a0 + a1) + (a2 + a3);
    } else if (tid < GD * 27 + GD) {
        const int o = tid - GD * 27;
        float a0 = s_bh[o], a1 = 0.f, a2 = 0.f, a3 = 0.f;
        #pragma unroll
        for (int c = 0; c < FEAT; c += 4) {
            a0 += s_wh[(c    ) * GD + o] * s_be[c    ];
            a1 += s_wh[(c + 1) * GD + o] * s_be[c + 1];
            a2 += s_wh[(c + 2) * GD + o] * s_be[c + 2];
            a3 += s_wh[(c + 3) * GD + o] * s_be[c + 3];
        }
        sb[o] = (a0 + a1) + (a2 + a3);
    }
    __syncthreads();

    // ---- conv: 64 gaussians x 8 channels = 512 threads, all LDS-fed --------
    {
        const int g = tid >> 3;            // gaussian in tile [0,64)
        const int o = tid & 7;             // output channel
        const int lr = g >> 3, lc = g & 7;

        float acc = sb[o];
        #pragma unroll
        for (int ci = 0; ci < CIN; ++ci) {
            #pragma unroll
            for (int ky = 0; ky < 3; ++ky) {
                #pragma unroll
                for (int kx = 0; kx < 3; ++kx) {
                    acc += s_inp[ci][lr + ky][lc + kx]
                         * sw[o * 27 + ci * 9 + ky * 3 + kx];
                }
            }
        }
        spred[g * 9 + o] = acc;
    }
    __syncthreads();

    // ---- activations/covariance: 1 thread per gaussian, write to global ----
    if (tid < 64) {
        const int lr = tid >> 3, lc = tid & 7;
        const int h = r0 + lr;
        const int w = c0 + lc;

        float pred[GD];
        #pragma unroll
        for (int o = 0; o < GD; ++o) pred[o] = spred[tid * 9 + o];

        const float theta = (1.f / (1.f + __expf(-pred[3]))) * 6.283185307179586f;
        const float s0 = (1.f / (1.f + __expf(-pred[4]))) * 0.5f + 1e-6f;
        const float s1 = (1.f / (1.f + __expf(-pred[5]))) * 0.5f + 1e-6f;
        const float off0 = tanhf(pred[6]);
        const float off1 = tanhf(pred[7]);

        const float c = __cosf(theta), s = __sinf(theta);
        const float v0 = s0 * s0, v1 = s1 * s1;
        const float S00 = c * c * v0 + s * s * v1;
        const float S01 = c * s * (v0 - v1);
        const float S11 = s * s * v0 + c * c * v1;
        const float det = S00 * S11 - S01 * S01;
        const float inv_det = 1.f / det;

        const float coord0 = 2.0f * (float)w / (float)Ww - 1.0f;
        const float coord1 = 2.0f * (float)h / (float)Hh - 1.0f;
        const float x_ndc = coord0 + 2.0f * off0 / (float)Ww - 1.0f / (float)Ww;
        const float y_ndc = coord1 + 2.0f * off1 / (float)Hh - 1.0f / (float)Hh;

        GParam g;
        g.cx = 0.5f * (float)Ww * (x_ndc + 1.0f) - 0.5f;
        g.cy = 0.5f * (float)Hh * (y_ndc + 1.0f) - 0.5f;
        g.ca =  S11 * inv_det;
        g.cb = -S01 * inv_det;
        g.cc =  S00 * inv_det;
        g.r0 = pred[0]; g.r1 = pred[1]; g.r2 = pred[2];
        g_gauss[h * Ww + w] = g;
    }

    // ---- sense-reversing grid barrier (state self-restores per replay) -----
    __threadfence();                 // release g_gauss
    __syncthreads();                 // block done writing
    if (tid == 0) {
        const int my_sense = *(volatile int*)&g_sense;   // read BEFORE arriving
        if (atomicAdd(&g_count, 1) == NB - 1) {
            g_count = 0;                                 // reset for next replay
            __threadfence();
            atomicExch(&g_sense, my_sense ^ 1);          // release everyone
        } else {
            while (*(volatile int*)&g_sense == my_sense) { }
        }
        __threadfence();             // acquire g_gauss
    }
    __syncthreads();

    // ---- raster: 64 pixels x 8 lanes over the EXACT 5x5 window -------------
    // cx = w + tanh(off) - 1 in (w-2, w); survivors need |cx-px| <= 1.6646
    // => contributing gaussian cols lie in [px-1, px+3] (rows symmetric).
    {
        const int pi  = tid >> 3;
        const int sub = tid & 7;
        const int pr = pi >> 3, pc = pi & 7;
        const int py = r0 + pr, px = c0 + pc;
        const float fpx = (float)px;
        const float fpy = (float)py;

        float a0 = 0.f, a1 = 0.f, a2 = 0.f;

        #pragma unroll
        for (int j = sub; j < 25; j += 8) {
            const int gh = py - 1 + j / 5;
            const int gw = px - 1 + j % 5;
            if ((unsigned)gh >= Hh || (unsigned)gw >= Ww) continue;
            const float4* q = reinterpret_cast<const float4*>(&g_gauss[gh * Ww + gw]);
            const float4 q0 = q[0];      // cx, cy, ca, cb
            const float4 q1 = q[1];      // cc, r0, r1, r2
            const float dx = q0.x - fpx;
            const float dy = q0.y - fpy;
            const float sigma = 0.5f * (q0.z * dx * dx + q1.x * dy * dy) + q0.w * dx * dy;
            if (!(sigma >= 0.f) || sigma > LN255) continue;
            const float alpha = fminf(0.999f, __expf(-sigma));
            a0 += alpha * q1.y;
            a1 += alpha * q1.z;
            a2 += alpha * q1.w;
        }

        #pragma unroll
        for (int m = 1; m < 8; m <<= 1) {
            a0 += __shfl_xor_sync(0xFFFFFFFFu, a0, m);
            a1 += __shfl_xor_sync(0xFFFFFFFFu, a1, m);
            a2 += __shfl_xor_sync(0xFFFFFFFFu, a2, m);
        }

        const int p = py * Ww + px;
        if (sub == 0)      out[0 * HW + p] = fminf(fmaxf(a0, 0.f), 1.f);
        else if (sub == 1) out[1 * HW + p] = fminf(fmaxf(a1, 0.f), 1.f);
        else if (sub == 2) out[2 * HW + p] = fminf(fmaxf(a2, 0.f), 1.f);
    }
}

// ---------------------------------------------------------------------------
extern "C" void kernel_launch(void* const* d_in, const int* in_sizes, int n_in,
                              void* d_out, int out_size)
{
    const float* inp    = (const float*)d_in[0];
    const float* w_enc  = (const float*)d_in[1];
    const float* b_enc  = (const float*)d_in[2];
    const float* w_head = (const float*)d_in[3];
    const float* b_head = (const float*)d_in[4];
    float* out = (float*)d_out;

    fused_kernel<<<NB, NT>>>(inp, w_enc, b_enc, w_head, b_head, out);
}

// round 12
// speedup vs baseline: 1.7575x; 1.7575x over previous
#include <cuda_runtime.h>
#include <math.h>

// Problem constants (B=1, C_IN=3, H=W=96, FEAT=64, GDIM=8, BLOCK=16)
#define Hh   96
#define Ww   96
#define HW   (96 * 96)
#define GD   8
#define FEAT 64
#define CIN  3

#define NB   144   // blocks: <=148 SMs, 1 block/SM -> all co-resident in wave 1
#define NT   512   // threads/block: 64 gaussians x 8 outputs; 64 pixels x 8 lanes

#define LN255 5.5412635f   // ln(255); alpha >= 1/255  <=>  sigma <= ln(255)

// 32-byte gaussian record (tile bounds proven redundant: radius >= 2 always,
// and any sigma-gate survivor has |d| <= 1.665 < radius => tile test passes).
struct __align__(16) GParam {
    float cx, cy, ca, cb, cc, r0, r1, r2;
};

__device__ GParam g_gauss[HW];   // 288 KB scratch (device global: no allocations)
__device__ int    g_arrive = 0;  // grid barrier counters (self-resetting per launch)
__device__ int    g_depart = 0;

// ---------------------------------------------------------------------------
// Single fused kernel: stage weights -> collapse conv+head -> per-gaussian
// params -> device-wide barrier -> rasterize over the EXACT 5x5 window.
// (Structure identical to the 13.3us R9 kernel; only the raster window and
//  its index arithmetic changed: 49 -> 25 candidates, all removed ones
//  provably zero-weight.)
// ---------------------------------------------------------------------------
__global__ __launch_bounds__(NT)
void fused_kernel(const float* __restrict__ inp,
                  const float* __restrict__ w_enc,
                  const float* __restrict__ b_enc,
                  const float* __restrict__ w_head,
                  const float* __restrict__ b_head,
                  float* __restrict__ out)
{
    __shared__ float s_we[FEAT * 27];   // w_enc  [c*27 + k]
    __shared__ float s_wh[FEAT * GD];   // w_head TRANSPOSED [c*8 + o] (bank-friendly)
    __shared__ float s_be[FEAT];
    __shared__ float s_bh[GD];
    __shared__ float sw[GD * 27];       // collapsed weights [o*27 + k]
    __shared__ float sb[GD];
    __shared__ float spred[64 * GD];    // per-gaussian raw preds [gi*8 + o]

    const int tid = threadIdx.x;
    const int bid = blockIdx.x;

    // ---- stage raw weights to shared (one coalesced cold-DRAM trip) --------
    for (int t = tid; t < FEAT * 27; t += NT) s_we[t] = __ldg(&w_enc[t]);
    {   // transpose w_head into [c][o]
        const int c = tid >> 3, o = tid & 7;           // tid < 512 == FEAT*GD
        s_wh[c * GD + o] = __ldg(&w_head[o * FEAT + c]);
    }
    if (tid < FEAT) s_be[tid] = __ldg(&b_enc[tid]);
    if (tid < GD)   s_bh[tid] = __ldg(&b_head[tid]);
    __syncthreads();

    // ---- collapse: w_eff[o,k] = sum_c w_head[o,c] * w_enc[c,k] -------------
    if (tid < GD * 27) {
        const int o = tid / 27, k = tid % 27;
        float a0 = 0.f, a1 = 0.f, a2 = 0.f, a3 = 0.f;
        #pragma unroll
        for (int c = 0; c < FEAT; c += 4) {
            a0 += s_wh[(c    ) * GD + o] * s_we[(c    ) * 27 + k];
            a1 += s_wh[(c + 1) * GD + o] * s_we[(c + 1) * 27 + k];
            a2 += s_wh[(c + 2) * GD + o] * s_we[(c + 2) * 27 + k];
            a3 += s_wh[(c + 3) * GD + o] * s_we[(c + 3) * 27 + k];
        }
        sw[tid] = (a0 + a1) + (a2 + a3);
    } else if (tid < GD * 27 + GD) {
        const int o = tid - GD * 27;
        float acc = s_bh[o];
        #pragma unroll
        for (int c = 0; c < FEAT; ++c)
            acc += s_wh[c * GD + o] * s_be[c];
        sb[o] = acc;
    }
    __syncthreads();

    // ---- phase A1: conv, 8 threads per gaussian (27 MACs each) -------------
    {
        const int gi = tid >> 3;          // gaussian within block [0,64)
        const int o  = tid & 7;           // output channel
        const int p  = bid * 64 + gi;     // [0, HW)
        const int w  = p % Ww;
        const int h  = p / Ww;

        float acc = sb[o];
        #pragma unroll
        for (int ci = 0; ci < CIN; ++ci) {
            #pragma unroll
            for (int ky = 0; ky < 3; ++ky) {
                const int y = h + ky - 1;
                #pragma unroll
                for (int kx = 0; kx < 3; ++kx) {
                    const int x = w + kx - 1;
                    float v = 0.f;
                    if (y >= 0 && y < Hh && x >= 0 && x < Ww)
                        v = __ldg(&inp[ci * HW + y * Ww + x]);
                    acc += v * sw[o * 27 + ci * 9 + ky * 3 + kx];
                }
            }
        }
        spred[gi * GD + o] = acc;
    }
    __syncthreads();

    // ---- phase A2: activation/covariance chain, 1 thread per gaussian ------
    if (tid < 64) {
        const int p = bid * 64 + tid;
        const int w = p % Ww;
        const int h = p / Ww;
        float pred[GD];
        #pragma unroll
        for (int o = 0; o < GD; ++o) pred[o] = spred[tid * GD + o];

        const float theta = (1.f / (1.f + __expf(-pred[3]))) * 6.283185307179586f;
        const float s0 = (1.f / (1.f + __expf(-pred[4]))) * 0.5f + 1e-6f;
        const float s1 = (1.f / (1.f + __expf(-pred[5]))) * 0.5f + 1e-6f;
        const float off0 = tanhf(pred[6]);
        const float off1 = tanhf(pred[7]);

        const float c = __cosf(theta), s = __sinf(theta);
        const float v0 = s0 * s0, v1 = s1 * s1;
        const float S00 = c * c * v0 + s * s * v1;
        const float S01 = c * s * (v0 - v1);
        const float S11 = s * s * v0 + c * c * v1;
        const float det = S00 * S11 - S01 * S01;
        const float inv_det = 1.f / det;

        const float coord0 = 2.0f * (float)w / (float)Ww - 1.0f;
        const float coord1 = 2.0f * (float)h / (float)Hh - 1.0f;
        const float x_ndc = coord0 + 2.0f * off0 / (float)Ww - 1.0f / (float)Ww;
        const float y_ndc = coord1 + 2.0f * off1 / (float)Hh - 1.0f / (float)Hh;

        GParam g;
        g.cx = 0.5f * (float)Ww * (x_ndc + 1.0f) - 0.5f;
        g.cy = 0.5f * (float)Hh * (y_ndc + 1.0f) - 0.5f;
        g.ca =  S11 * inv_det;
        g.cb = -S01 * inv_det;
        g.cc =  S00 * inv_det;
        g.r0 = pred[0]; g.r1 = pred[1]; g.r2 = pred[2];
        g_gauss[p] = g;
    }

    // ---- device-wide barrier (all NB blocks resident in wave 1) ------------
    __threadfence();                     // publish g_gauss GPU-wide
    __syncthreads();                     // whole block done writing
    if (tid == 0) {
        atomicAdd(&g_arrive, 1);
        while (*(volatile int*)&g_arrive < NB) { }
        __threadfence();
        atomicAdd(&g_depart, 1);         // "I will never read g_arrive again"
    }
    __syncthreads();                     // released; all g_gauss visible

    // ---- phase B: rasterize, 8 lanes per pixel, EXACT 5x5 window -----------
    // cx = w + tanh(off) - 1 in (w-2, w); sigma-gate survivors need
    // |cx - px| <= 1.6645  =>  contributing gaussian cols in [px-1, px+3]
    // (rows symmetric). The removed candidates are provably zero-weight.
    {
        const int gt  = bid * NT + tid;  // [0, 8*HW)
        const int p   = gt >> 3;
        const int sub = gt & 7;
        const int px = p % Ww;
        const int py = p / Ww;
        const float fpx = (float)px;
        const float fpy = (float)py;

        float a0 = 0.f, a1 = 0.f, a2 = 0.f;

        #pragma unroll
        for (int j = sub; j < 25; j += 8) {
            const int gh = py - 1 + j / 5;
            const int gw = px - 1 + j % 5;
            if ((unsigned)gh >= Hh || (unsigned)gw >= Ww) continue;
            const float4* q = reinterpret_cast<const float4*>(&g_gauss[gh * Ww + gw]);
            const float4 q0 = q[0];      // cx, cy, ca, cb
            const float4 q1 = q[1];      // cc, r0, r1, r2
            const float dx = q0.x - fpx;
            const float dy = q0.y - fpy;
            const float sigma = 0.5f * (q0.z * dx * dx + q1.x * dy * dy) + q0.w * dx * dy;
            if (!(sigma >= 0.f) || sigma > LN255) continue;
            const float alpha = fminf(0.999f, __expf(-sigma));
            a0 += alpha * q1.y;
            a1 += alpha * q1.z;
            a2 += alpha * q1.w;
        }

        #pragma unroll
        for (int m = 1; m < 8; m <<= 1) {
            a0 += __shfl_xor_sync(0xFFFFFFFFu, a0, m);
            a1 += __shfl_xor_sync(0xFFFFFFFFu, a1, m);
            a2 += __shfl_xor_sync(0xFFFFFFFFu, a2, m);
        }

        if (sub == 0)      out[0 * HW + p] = fminf(fmaxf(a0, 0.f), 1.f);
        else if (sub == 1) out[1 * HW + p] = fminf(fmaxf(a1, 0.f), 1.f);
        else if (sub == 2) out[2 * HW + p] = fminf(fmaxf(a2, 0.f), 1.f);
    }

    // ---- reset barrier counters for the next graph replay ------------------
    if (bid == 0 && tid == 0) {
        while (*(volatile int*)&g_depart < NB) { }   // nobody touches g_arrive anymore
        atomicExch(&g_arrive, 0);
        atomicExch(&g_depart, 0);
    }
}

// ---------------------------------------------------------------------------
extern "C" void kernel_launch(void* const* d_in, const int* in_sizes, int n_in,
                              void* d_out, int out_size)
{
    const float* inp    = (const float*)d_in[0];
    const float* w_enc  = (const float*)d_in[1];
    const float* b_enc  = (const float*)d_in[2];
    const float* w_head = (const float*)d_in[3];
    const float* b_head = (const float*)d_in[4];
    float* out = (float*)d_out;

    fused_kernel<<<NB, NT>>>(inp, w_enc, b_enc, w_head, b_head, out);
}